// round 12
// baseline (speedup 1.0000x reference)
// R12: resubmission of the audited R11 kernel (R11 died to infra, never ran).
// fgemm: warp tile 64x64 (2m x 2n, 128 thr/CTA, 2 CTAs/SM) to halve LDSM
// traffic per MAC (smem-BW bound per R10 analysis). Rest unchanged.
#include <cuda_runtime.h>
#include <cuda_bf16.h>
#include <cstdint>
#include <math.h>

// Problem constants
#define BATCH   32
#define SEQ     1024
#define INDIM   1024
#define DDIM    1024
#define MLPDIM  2048
#define NCLS    10
#define BSROWS  (BATCH * SEQ)     // 32768
#define KCAT    (2 * INDIM)       // 2048

// GEMM tiling
#define BM 128
#define BN 128
#define BK 32
#define NKCH (KCAT / BK)          // 64 k-chunks
#define XH   (INDIM / BK)         // 16 (chunks in first half)
#define ROWSTRIDE 40              // bf16 per smem row (32 data + 8 pad), 80 bytes
#define ARR_BYTES (128 * ROWSTRIDE * 2)      // 10240
#define STAGE_BYTES (4 * ARR_BYTES)          // 40960: Ahi, Alo, Bhi, Blo
#define SMEM_TOTAL (2 * STAGE_BYTES)         // 81920 -> 2 CTAs/SM

// recurrence segmentation
#define RSEG 8
#define SEGLEN (SEQ / RSEG)       // 128

// ---------------- scratch (device globals) ----------------
__device__ __align__(16) __nv_bfloat16 g_ahi[(size_t)BSROWS * INDIM];  // 64 MB
__device__ __align__(16) __nv_bfloat16 g_alo[(size_t)BSROWS * INDIM];  // 64 MB
__device__ __align__(16) __nv_bfloat16 g_bhi[(size_t)DDIM * KCAT];     // [n][k]
__device__ __align__(16) __nv_bfloat16 g_blo[(size_t)DDIM * KCAT];

__device__ float g_F[(size_t)BSROWS * DDIM];   // f = sigmoid(f_pre)
__device__ float g_segA[RSEG * BATCH * DDIM];
__device__ float g_segB[RSEG * BATCH * DDIM];
__device__ float g_c[BATCH * DDIM];
__device__ float g_h[BATCH * DDIM];
__device__ float g_q0[BATCH * MLPDIM];
__device__ float g_q1[BATCH * MLPDIM];

__device__ __forceinline__ float sigmoidf_(float v) {
    return 1.0f / (1.0f + expf(-v));
}
__device__ __forceinline__ uint32_t smem_u32(const void* p) {
    uint32_t a;
    asm("{ .reg .u64 t; cvta.to.shared.u64 t, %1; cvt.u32.u64 %0, t; }" : "=r"(a) : "l"(p));
    return a;
}
__device__ __forceinline__ void cpasync16z(uint32_t dst, const void* gsrc, uint32_t srcbytes) {
    asm volatile("cp.async.cg.shared.global [%0], [%1], 16, %2;"
                 :: "r"(dst), "l"(__cvta_generic_to_global(gsrc)), "r"(srcbytes) : "memory");
}
__device__ __forceinline__ void cp_commit() {
    asm volatile("cp.async.commit_group;" ::: "memory");
}
template <int N>
__device__ __forceinline__ void cp_wait() {
    asm volatile("cp.async.wait_group %0;" :: "n"(N) : "memory");
}
__device__ __forceinline__ void ldsm_x4(uint32_t* r, uint32_t addr) {
    asm volatile("ldmatrix.sync.aligned.m8n8.x4.shared.b16 {%0,%1,%2,%3}, [%4];"
                 : "=r"(r[0]), "=r"(r[1]), "=r"(r[2]), "=r"(r[3]) : "r"(addr));
}
__device__ __forceinline__ void mma_bf16(float* c, const uint32_t* a, const uint32_t* b) {
    asm volatile(
        "mma.sync.aligned.m16n8k16.row.col.f32.bf16.bf16.f32 "
        "{%0,%1,%2,%3}, {%4,%5,%6,%7}, {%8,%9}, {%0,%1,%2,%3};"
        : "+f"(c[0]), "+f"(c[1]), "+f"(c[2]), "+f"(c[3])
        : "r"(a[0]), "r"(a[1]), "r"(a[2]), "r"(a[3]), "r"(b[0]), "r"(b[1]));
}

// ---------------- convert x -> bf16 hi/lo [r][0:1024] ----------------
__global__ __launch_bounds__(256) void convert_x_kernel(const float* __restrict__ x)
{
    size_t idx = (size_t)blockIdx.x * blockDim.x + threadIdx.x;  // BSROWS*128
    size_t r = idx >> 7;
    int j = (int)(idx & 127) * 8;

    const float4* src = reinterpret_cast<const float4*>(x + r * INDIM + j);
    float4 v0 = src[0], v1 = src[1];
    float vs[8] = {v0.x, v0.y, v0.z, v0.w, v1.x, v1.y, v1.z, v1.w};

    uint32_t hw[4], lw[4];
    #pragma unroll
    for (int i = 0; i < 4; i++) {
        __nv_bfloat16 h0 = __float2bfloat16(vs[2*i]);
        __nv_bfloat16 h1 = __float2bfloat16(vs[2*i+1]);
        __nv_bfloat16 l0 = __float2bfloat16(vs[2*i]   - __bfloat162float(h0));
        __nv_bfloat16 l1 = __float2bfloat16(vs[2*i+1] - __bfloat162float(h1));
        hw[i] = (uint32_t)__bfloat16_as_ushort(h0) | ((uint32_t)__bfloat16_as_ushort(h1) << 16);
        lw[i] = (uint32_t)__bfloat16_as_ushort(l0) | ((uint32_t)__bfloat16_as_ushort(l1) << 16);
    }
    reinterpret_cast<uint4*>(g_ahi)[(r * INDIM + j) >> 3] = make_uint4(hw[0], hw[1], hw[2], hw[3]);
    reinterpret_cast<uint4*>(g_alo)[(r * INDIM + j) >> 3] = make_uint4(lw[0], lw[1], lw[2], lw[3]);
}

// ---------------- convert weights: Bcat^T [n][k] bf16 hi/lo ----------------
__global__ __launch_bounds__(256) void convert_w_kernel(
    const float* __restrict__ Ww, const float* __restrict__ Vw)
{
    __shared__ float s[32][33];
    int kt = blockIdx.x;     // 0..63
    int nt = blockIdx.y;     // 0..31
    int k0 = kt * 32, n0 = nt * 32;
    int tid = threadIdx.x;

    const float* src = (k0 < INDIM) ? (Ww + (size_t)k0 * (3 * DDIM))
                                    : (Vw + (size_t)(k0 - INDIM) * (3 * DDIM));
    #pragma unroll
    for (int i = 0; i < 4; i++) {
        int lin = tid + i * 256;
        int kk = lin >> 5, nn = lin & 31;
        s[kk][nn] = src[(size_t)kk * (3 * DDIM) + n0 + nn];
    }
    __syncthreads();

    #pragma unroll
    for (int i = 0; i < 2; i++) {
        int lin = tid + i * 256;
        int nn = lin >> 4;
        int kp = lin & 15;
        float a = s[kp * 2][nn], b = s[kp * 2 + 1][nn];
        __nv_bfloat16 h0 = __float2bfloat16(a);
        __nv_bfloat16 h1 = __float2bfloat16(b);
        __nv_bfloat16 l0 = __float2bfloat16(a - __bfloat162float(h0));
        __nv_bfloat16 l1 = __float2bfloat16(b - __bfloat162float(h1));
        size_t off = ((size_t)(n0 + nn) * KCAT + k0 + kp * 2) >> 1;
        reinterpret_cast<uint32_t*>(g_bhi)[off] =
            (uint32_t)__bfloat16_as_ushort(h0) | ((uint32_t)__bfloat16_as_ushort(h1) << 16);
        reinterpret_cast<uint32_t*>(g_blo)[off] =
            (uint32_t)__bfloat16_as_ushort(l0) | ((uint32_t)__bfloat16_as_ushort(l1) << 16);
    }
}

// ---------------- main GEMM: mma.sync bf16 3-pass split ----------------
// grid (8 n, 256 m), 128 threads = 4 warps (2 m x 2 n), warp tile 64x64.
// 2 CTAs/SM; 2-stage pipe; one __syncthreads per k-chunk.
__global__ __launch_bounds__(128, 2) void fgemm_mma_kernel(const float* __restrict__ Vb)
{
    extern __shared__ __align__(16) char smem[];
    const uint32_t sbase = smem_u32(smem);
    const int tid = threadIdx.x;
    const int wid = tid >> 5, lane = tid & 31;
    const int mwarp = wid >> 1, nwarp = wid & 1;
    const int g = lane >> 2, t4 = lane & 3;

    const size_t r0 = (size_t)blockIdx.y * BM;
    const int n0 = blockIdx.x * BN;

    // ldmatrix per-lane byte offsets (80B row stride; conflict-free)
    const uint32_t a_off = (((lane >> 3) & 1) * 8 + (lane & 7)) * 80 + (lane >> 4) * 16;
    const uint32_t b_off = (((lane >> 4) & 1) * 8 + (lane & 7)) * 80 + ((lane >> 3) & 1) * 16;

    float c[4][8][4];
    #pragma unroll
    for (int mt = 0; mt < 4; mt++)
        #pragma unroll
        for (int nt = 0; nt < 8; nt++)
            #pragma unroll
            for (int i = 0; i < 4; i++) c[mt][nt][i] = 0.0f;

    // prefetch: 2048 16B chunks per stage, 128 threads -> 16 each
    auto prefetch = [&](int kc, int s) {
        const uint32_t st = sbase + (uint32_t)s * STAGE_BYTES;
        #pragma unroll
        for (int i = 0; i < 16; i++) {
            int cidx = tid + i * 128;
            if (cidx < 1024) {
                // A: hi/lo, 128 rows x 4 chunks
                int hilo = cidx >> 9;
                int rem  = cidx & 511;
                int row  = rem >> 2;
                int ch   = rem & 3;
                uint32_t dst = st + (uint32_t)hilo * ARR_BYTES + row * 80 + ch * 16;
                const __nv_bfloat16* base = hilo ? g_alo : g_ahi;
                const void* src;
                uint32_t sz = 16;
                if (kc < XH) {
                    src = base + (r0 + row) * INDIM + kc * BK + ch * 8;
                } else {
                    bool z = (row == 0) && ((r0 & (SEQ - 1)) == 0);
                    src = z ? (const void*)base
                            : (const void*)(base + (r0 + row - 1) * INDIM + (kc - XH) * BK + ch * 8);
                    sz = z ? 0u : 16u;
                }
                cpasync16z(dst, src, sz);
            } else {
                // B: hi/lo, 128 rows x 4 chunks
                int cidx2 = cidx - 1024;
                int hilo = cidx2 >> 9;
                int rem  = cidx2 & 511;
                int row  = rem >> 2;
                int ch   = rem & 3;
                uint32_t dst = st + (uint32_t)(2 + hilo) * ARR_BYTES + row * 80 + ch * 16;
                const __nv_bfloat16* base = hilo ? g_blo : g_bhi;
                cpasync16z(dst, base + (size_t)(n0 + row) * KCAT + kc * BK + ch * 8, 16);
            }
        }
        cp_commit();
    };

    prefetch(0, 0);

    for (int kc = 0; kc < NKCH; kc++) {
        int s = kc & 1;
        cp_wait<0>();
        __syncthreads();
        // safe: stage (kc+1)&1 was last read at iteration kc-1; the barrier
        // above proves all warps have left it.
        if (kc + 1 < NKCH) prefetch(kc + 1, s ^ 1);

        const uint32_t sA_hi = sbase + (uint32_t)s * STAGE_BYTES;
        const uint32_t sA_lo = sA_hi + ARR_BYTES;
        const uint32_t sB_hi = sA_hi + 2 * ARR_BYTES;
        const uint32_t sB_lo = sA_hi + 3 * ARR_BYTES;

        #pragma unroll
        for (int h = 0; h < 2; h++) {
            uint32_t aH[4][4], aL[4][4];
            #pragma unroll
            for (int mt = 0; mt < 4; mt++) {
                uint32_t rb = (uint32_t)(mwarp * 64 + mt * 16) * 80 + h * 32;
                ldsm_x4(aH[mt], sA_hi + rb + a_off);
                ldsm_x4(aL[mt], sA_lo + rb + a_off);
            }
            #pragma unroll
            for (int p = 0; p < 4; p++) {
                uint32_t bh[4], bl[4];
                uint32_t nb = (uint32_t)(nwarp * 64 + p * 16) * 80 + h * 32;
                ldsm_x4(bh, sB_hi + nb + b_off);
                ldsm_x4(bl, sB_lo + nb + b_off);
                #pragma unroll
                for (int mt = 0; mt < 4; mt++) {
                    // pass Ah*Bh
                    mma_bf16(c[mt][2*p],   aH[mt], bh);
                    mma_bf16(c[mt][2*p+1], aH[mt], bh + 2);
                    // pass Ah*Bl
                    mma_bf16(c[mt][2*p],   aH[mt], bl);
                    mma_bf16(c[mt][2*p+1], aH[mt], bl + 2);
                    // pass Al*Bh
                    mma_bf16(c[mt][2*p],   aL[mt], bh);
                    mma_bf16(c[mt][2*p+1], aL[mt], bh + 2);
                }
            }
        }
    }

    // epilogue: bias + sigmoid -> g_F
    #pragma unroll
    for (int mt = 0; mt < 4; mt++) {
        #pragma unroll
        for (int nt = 0; nt < 8; nt++) {
            size_t m = r0 + mwarp * 64 + mt * 16 + g;
            int n = n0 + nwarp * 64 + nt * 8 + t4 * 2;
            float b0 = Vb[n], b1 = Vb[n + 1];
            float2 v0, v1;
            v0.x = sigmoidf_(c[mt][nt][0] + b0);
            v0.y = sigmoidf_(c[mt][nt][1] + b1);
            v1.x = sigmoidf_(c[mt][nt][2] + b0);
            v1.y = sigmoidf_(c[mt][nt][3] + b1);
            *reinterpret_cast<float2*>(g_F + m * DDIM + n) = v0;
            *reinterpret_cast<float2*>(g_F + (m + 8) * DDIM + n) = v1;
        }
    }
}

// ---------------- recurrence, segmented (affine composition) ----------------
__global__ __launch_bounds__(256) void recur_part_kernel()
{
    int gidx = blockIdx.x * blockDim.x + threadIdx.x;   // 0..262143
    int seg = gidx >> 15;
    int r   = gidx & 32767;
    int b = r >> 10;
    int d = r & 1023;
    const float* p = g_F + ((size_t)b * SEQ + seg * SEGLEN) * DDIM + d;
    float A = 1.0f, B = 0.0f;
    #pragma unroll 8
    for (int t = 0; t < SEGLEN; t++) {
        float f = p[(size_t)t * DDIM];
        A *= f;
        B = f * (B + 1.0f);
    }
    g_segA[gidx] = A;
    g_segB[gidx] = B;
}

__global__ __launch_bounds__(256) void recur_combine_kernel()
{
    int idx = blockIdx.x * blockDim.x + threadIdx.x;    // 0..32767
    float c = 0.0f;
    #pragma unroll
    for (int s = 0; s < RSEG; s++)
        c = g_segA[s * (BATCH * DDIM) + idx] * c + g_segB[s * (BATCH * DDIM) + idx];
    g_c[idx] = c;
}

// ---------------- o at last timestep + h ----------------
__global__ __launch_bounds__(256) void oh_kernel(
    const float* __restrict__ x,
    const float* __restrict__ Ww,
    const float* __restrict__ Vw,
    const float* __restrict__ Vb)
{
    int idx = blockIdx.x * blockDim.x + threadIdx.x;
    int b = idx >> 10;
    int d = idx & 1023;
    const float* xlast = x + ((size_t)b * SEQ + (SEQ - 1)) * INDIM;
    const float* xprev = xlast - INDIM;
    const float* wcol  = Ww + 2 * DDIM + d;
    const float* vcol  = Vw + 2 * DDIM + d;
    float acc = Vb[2 * DDIM + d];
    #pragma unroll 4
    for (int k = 0; k < INDIM; k++) {
        acc += xlast[k] * wcol[(size_t)k * (3 * DDIM)];
        acc += xprev[k] * vcol[(size_t)k * (3 * DDIM)];
    }
    g_h[idx] = g_c[idx] * sigmoidf_(acc);
}

// ---------------- MLP layers (M=32, N=2048) ----------------
__global__ __launch_bounds__(256) void mlp_kernel(
    const float* __restrict__ W,
    const float* __restrict__ bias,
    int KDIM, int layer)
{
    const float* Ain = (layer == 0) ? g_h  : g_q0;
    float*       out = (layer == 0) ? g_q0 : g_q1;

    __shared__ float As[32][33];
    __shared__ float Bs[32][33];

    int n0   = blockIdx.x * 32;
    int tid  = threadIdx.x;
    int tcol = tid & 31;
    int trow = tid >> 5;

    float acc[4] = {0.f, 0.f, 0.f, 0.f};

    for (int k0 = 0; k0 < KDIM; k0 += 32) {
        #pragma unroll
        for (int i = 0; i < 4; i++) {
            int lin = tid + i * 256;
            int m = lin >> 5, kk = lin & 31;
            As[m][kk] = Ain[(size_t)m * KDIM + k0 + kk];
            Bs[m][kk] = W[(size_t)(k0 + m) * MLPDIM + n0 + kk];
        }
        __syncthreads();
        #pragma unroll
        for (int kk = 0; kk < 32; kk++) {
            float bv = Bs[kk][tcol];
            #pragma unroll
            for (int i = 0; i < 4; i++)
                acc[i] += As[trow * 4 + i][kk] * bv;
        }
        __syncthreads();
    }
    #pragma unroll
    for (int i = 0; i < 4; i++) {
        float v = acc[i] + bias[n0 + tcol];
        out[(size_t)(trow * 4 + i) * MLPDIM + n0 + tcol] = fmaxf(v, 0.0f);
    }
}

// ---------------- head ----------------
__global__ __launch_bounds__(256) void head_kernel(
    const float* __restrict__ W2,
    const float* __restrict__ b2,
    float* __restrict__ out)
{
    int warp = (blockIdx.x * blockDim.x + threadIdx.x) >> 5;
    int lane = threadIdx.x & 31;
    if (warp >= BATCH * NCLS) return;
    int m = warp / NCLS;
    int n = warp % NCLS;
    const float* a = g_q1 + (size_t)m * MLPDIM;
    float s = 0.0f;
    for (int k = lane; k < MLPDIM; k += 32)
        s += a[k] * W2[(size_t)k * NCLS + n];
    #pragma unroll
    for (int off = 16; off; off >>= 1)
        s += __shfl_xor_sync(0xffffffffu, s, off);
    if (lane == 0) out[warp] = s + b2[n];
}

// ============================================================================
extern "C" void kernel_launch(void* const* d_in, const int* in_sizes, int n_in,
                              void* d_out, int out_size)
{
    const float* x   = (const float*)d_in[0];
    const float* Ww  = (const float*)d_in[1];
    const float* Vw  = (const float*)d_in[2];
    const float* Vb  = (const float*)d_in[3];
    const float* l0w = (const float*)d_in[4];
    const float* l0b = (const float*)d_in[5];
    const float* l1w = (const float*)d_in[6];
    const float* l1b = (const float*)d_in[7];
    const float* l2w = (const float*)d_in[8];
    const float* l2b = (const float*)d_in[9];
    float* out = (float*)d_out;

    cudaFuncSetAttribute(fgemm_mma_kernel,
                         cudaFuncAttributeMaxDynamicSharedMemorySize, SMEM_TOTAL);

    // 0. convert to bf16 hi/lo scratch
    convert_x_kernel<<<(BSROWS * 128) / 256, 256>>>(x);
    convert_w_kernel<<<dim3(KCAT / 32, DDIM / 32), 256>>>(Ww, Vw);

    // 1. f = sigmoid(x@Wf + xprev@Vf + b) via bf16-split mma.sync
    fgemm_mma_kernel<<<dim3(DDIM / BN, BSROWS / BM), 128, SMEM_TOTAL>>>(Vb);

    // 2. recurrence -> c_last (segmented)
    recur_part_kernel<<<(RSEG * BATCH * DDIM) / 256, 256>>>();
    recur_combine_kernel<<<(BATCH * DDIM) / 256, 256>>>();

    // 3. o at last timestep, h = c * o
    oh_kernel<<<(BATCH * DDIM) / 256, 256>>>(x, Ww, Vw, Vb);

    // 4. MLP
    mlp_kernel<<<MLPDIM / 32, 256>>>(l0w, l0b, DDIM,   0);
    mlp_kernel<<<MLPDIM / 32, 256>>>(l1w, l1b, MLPDIM, 1);

    // 5. head
    head_kernel<<<(BATCH * NCLS * 32 + 255) / 256, 256>>>(l2w, l2b, out);
}

// round 13
// speedup vs baseline: 1.3309x; 1.3309x over previous
// R13: fgemm precision scheme change: 3-pass bf16 hi/lo -> 2-pass fp16
// (A single fp16, B fp16 hi/lo). -33% MMA volume (legacy HMMA pipe is the
// measured wall). Warp layout reverted to the R10-proven 8-warp 32x64.
#include <cuda_runtime.h>
#include <cuda_fp16.h>
#include <cstdint>
#include <math.h>

// Problem constants
#define BATCH   32
#define SEQ     1024
#define INDIM   1024
#define DDIM    1024
#define MLPDIM  2048
#define NCLS    10
#define BSROWS  (BATCH * SEQ)     // 32768
#define KCAT    (2 * INDIM)       // 2048

// GEMM tiling
#define BM 128
#define BN 128
#define BK 32
#define NKCH (KCAT / BK)          // 64 k-chunks
#define XH   (INDIM / BK)         // 16 (chunks in first half)
#define ROWSTRIDE 40              // fp16 per smem row (32 data + 8 pad), 80 bytes
#define ARR_BYTES (128 * ROWSTRIDE * 2)      // 10240
#define STAGE_BYTES (3 * ARR_BYTES)          // 30720: A, Bhi, Blo
#define SMEM_TOTAL (2 * STAGE_BYTES)         // 61440 -> 2 CTAs/SM

// recurrence segmentation
#define RSEG 8
#define SEGLEN (SEQ / RSEG)       // 128

// ---------------- scratch (device globals) ----------------
__device__ __align__(16) __half g_ah [(size_t)BSROWS * INDIM];   // 64 MB (A fp16)
__device__ __align__(16) __half g_bhi[(size_t)DDIM * KCAT];      // [n][k] B hi
__device__ __align__(16) __half g_blo[(size_t)DDIM * KCAT];      // [n][k] B lo

__device__ float g_F[(size_t)BSROWS * DDIM];   // f = sigmoid(f_pre)
__device__ float g_segA[RSEG * BATCH * DDIM];
__device__ float g_segB[RSEG * BATCH * DDIM];
__device__ float g_c[BATCH * DDIM];
__device__ float g_h[BATCH * DDIM];
__device__ float g_q0[BATCH * MLPDIM];
__device__ float g_q1[BATCH * MLPDIM];

__device__ __forceinline__ float sigmoidf_(float v) {
    return 1.0f / (1.0f + expf(-v));
}
__device__ __forceinline__ uint32_t smem_u32(const void* p) {
    uint32_t a;
    asm("{ .reg .u64 t; cvta.to.shared.u64 t, %1; cvt.u32.u64 %0, t; }" : "=r"(a) : "l"(p));
    return a;
}
__device__ __forceinline__ void cpasync16z(uint32_t dst, const void* gsrc, uint32_t srcbytes) {
    asm volatile("cp.async.cg.shared.global [%0], [%1], 16, %2;"
                 :: "r"(dst), "l"(__cvta_generic_to_global(gsrc)), "r"(srcbytes) : "memory");
}
__device__ __forceinline__ void cp_commit() {
    asm volatile("cp.async.commit_group;" ::: "memory");
}
template <int N>
__device__ __forceinline__ void cp_wait() {
    asm volatile("cp.async.wait_group %0;" :: "n"(N) : "memory");
}
__device__ __forceinline__ void ldsm_x4(uint32_t* r, uint32_t addr) {
    asm volatile("ldmatrix.sync.aligned.m8n8.x4.shared.b16 {%0,%1,%2,%3}, [%4];"
                 : "=r"(r[0]), "=r"(r[1]), "=r"(r[2]), "=r"(r[3]) : "r"(addr));
}
__device__ __forceinline__ void mma_f16(float* c, const uint32_t* a, const uint32_t* b) {
    asm volatile(
        "mma.sync.aligned.m16n8k16.row.col.f32.f16.f16.f32 "
        "{%0,%1,%2,%3}, {%4,%5,%6,%7}, {%8,%9}, {%0,%1,%2,%3};"
        : "+f"(c[0]), "+f"(c[1]), "+f"(c[2]), "+f"(c[3])
        : "r"(a[0]), "r"(a[1]), "r"(a[2]), "r"(a[3]), "r"(b[0]), "r"(b[1]));
}

// ---------------- convert x -> fp16 [r][0:1024] ----------------
__global__ __launch_bounds__(256) void convert_x_kernel(const float* __restrict__ x)
{
    size_t idx = (size_t)blockIdx.x * blockDim.x + threadIdx.x;  // BSROWS*128
    size_t r = idx >> 7;
    int j = (int)(idx & 127) * 8;

    const float4* src = reinterpret_cast<const float4*>(x + r * INDIM + j);
    float4 v0 = src[0], v1 = src[1];
    float vs[8] = {v0.x, v0.y, v0.z, v0.w, v1.x, v1.y, v1.z, v1.w};

    uint32_t hw[4];
    #pragma unroll
    for (int i = 0; i < 4; i++) {
        __half h0 = __float2half_rn(vs[2*i]);
        __half h1 = __float2half_rn(vs[2*i+1]);
        hw[i] = (uint32_t)__half_as_ushort(h0) | ((uint32_t)__half_as_ushort(h1) << 16);
    }
    reinterpret_cast<uint4*>(g_ah)[(r * INDIM + j) >> 3] = make_uint4(hw[0], hw[1], hw[2], hw[3]);
}

// ---------------- convert weights: Bcat^T [n][k] fp16 hi/lo ----------------
__global__ __launch_bounds__(256) void convert_w_kernel(
    const float* __restrict__ Ww, const float* __restrict__ Vw)
{
    __shared__ float s[32][33];
    int kt = blockIdx.x;     // 0..63
    int nt = blockIdx.y;     // 0..31
    int k0 = kt * 32, n0 = nt * 32;
    int tid = threadIdx.x;

    const float* src = (k0 < INDIM) ? (Ww + (size_t)k0 * (3 * DDIM))
                                    : (Vw + (size_t)(k0 - INDIM) * (3 * DDIM));
    #pragma unroll
    for (int i = 0; i < 4; i++) {
        int lin = tid + i * 256;
        int kk = lin >> 5, nn = lin & 31;
        s[kk][nn] = src[(size_t)kk * (3 * DDIM) + n0 + nn];
    }
    __syncthreads();

    #pragma unroll
    for (int i = 0; i < 2; i++) {
        int lin = tid + i * 256;
        int nn = lin >> 4;
        int kp = lin & 15;
        float a = s[kp * 2][nn], b = s[kp * 2 + 1][nn];
        __half h0 = __float2half_rn(a);
        __half h1 = __float2half_rn(b);
        __half l0 = __float2half_rn(a - __half2float(h0));
        __half l1 = __float2half_rn(b - __half2float(h1));
        size_t off = ((size_t)(n0 + nn) * KCAT + k0 + kp * 2) >> 1;
        reinterpret_cast<uint32_t*>(g_bhi)[off] =
            (uint32_t)__half_as_ushort(h0) | ((uint32_t)__half_as_ushort(h1) << 16);
        reinterpret_cast<uint32_t*>(g_blo)[off] =
            (uint32_t)__half_as_ushort(l0) | ((uint32_t)__half_as_ushort(l1) << 16);
    }
}

// ---------------- main GEMM: mma.sync fp16 2-pass (A, B hi/lo) ----------------
// grid (8 n, 256 m), 256 threads = 8 warps (4 m x 2 n), warp tile 32x64.
// 2 CTAs/SM; 2-stage pipe; one __syncthreads per k-chunk.
__global__ __launch_bounds__(256, 2) void fgemm_mma_kernel(const float* __restrict__ Vb)
{
    extern __shared__ __align__(16) char smem[];
    const uint32_t sbase = smem_u32(smem);
    const int tid = threadIdx.x;
    const int wid = tid >> 5, lane = tid & 31;
    const int mwarp = wid >> 1, nwarp = wid & 1;
    const int g = lane >> 2, t4 = lane & 3;

    const size_t r0 = (size_t)blockIdx.y * BM;
    const int n0 = blockIdx.x * BN;

    // ldmatrix per-lane byte offsets (80B row stride; conflict-free)
    const uint32_t a_off = (((lane >> 3) & 1) * 8 + (lane & 7)) * 80 + (lane >> 4) * 16;
    const uint32_t b_off = (((lane >> 4) & 1) * 8 + (lane & 7)) * 80 + ((lane >> 3) & 1) * 16;

    float c[2][8][4];
    #pragma unroll
    for (int mt = 0; mt < 2; mt++)
        #pragma unroll
        for (int nt = 0; nt < 8; nt++)
            #pragma unroll
            for (int i = 0; i < 4; i++) c[mt][nt][i] = 0.0f;

    // prefetch: 1536 16B chunks per stage (A, Bhi, Blo), 256 threads -> 6 each
    auto prefetch = [&](int kc, int s) {
        const uint32_t st = sbase + (uint32_t)s * STAGE_BYTES;
        #pragma unroll
        for (int i = 0; i < 6; i++) {
            int cidx = tid + i * 256;
            if (cidx < 512) {
                // A: 128 rows x 4 chunks
                int row = cidx >> 2;
                int ch  = cidx & 3;
                uint32_t dst = st + row * 80 + ch * 16;
                const void* src;
                uint32_t sz = 16;
                if (kc < XH) {
                    src = g_ah + (r0 + row) * INDIM + kc * BK + ch * 8;
                } else {
                    bool z = (row == 0) && ((r0 & (SEQ - 1)) == 0);
                    src = z ? (const void*)g_ah
                            : (const void*)(g_ah + (r0 + row - 1) * INDIM + (kc - XH) * BK + ch * 8);
                    sz = z ? 0u : 16u;
                }
                cpasync16z(dst, src, sz);
            } else {
                // B: hi/lo, 128 rows x 4 chunks each
                int cidx2 = cidx - 512;
                int hilo = cidx2 >> 9;          // 0 = hi, 1 = lo
                int rem  = cidx2 & 511;
                int row  = rem >> 2;
                int ch   = rem & 3;
                uint32_t dst = st + (uint32_t)(1 + hilo) * ARR_BYTES + row * 80 + ch * 16;
                const __half* base = hilo ? g_blo : g_bhi;
                cpasync16z(dst, base + (size_t)(n0 + row) * KCAT + kc * BK + ch * 8, 16);
            }
        }
        cp_commit();
    };

    prefetch(0, 0);

    for (int kc = 0; kc < NKCH; kc++) {
        int s = kc & 1;
        cp_wait<0>();
        __syncthreads();
        // safe: stage (kc+1)&1 was last read at iteration kc-1; the barrier
        // above proves all warps have left it.
        if (kc + 1 < NKCH) prefetch(kc + 1, s ^ 1);

        const uint32_t sA    = sbase + (uint32_t)s * STAGE_BYTES;
        const uint32_t sB_hi = sA + ARR_BYTES;
        const uint32_t sB_lo = sA + 2 * ARR_BYTES;

        #pragma unroll
        for (int h = 0; h < 2; h++) {
            uint32_t aH[2][4];
            #pragma unroll
            for (int mt = 0; mt < 2; mt++) {
                uint32_t rb = (uint32_t)(mwarp * 32 + mt * 16) * 80 + h * 32;
                ldsm_x4(aH[mt], sA + rb + a_off);
            }
            #pragma unroll
            for (int p = 0; p < 4; p++) {
                uint32_t bh[4], bl[4];
                uint32_t nb = (uint32_t)(nwarp * 64 + p * 16) * 80 + h * 32;
                ldsm_x4(bh, sB_hi + nb + b_off);
                ldsm_x4(bl, sB_lo + nb + b_off);
                // pass A*Bh
                mma_f16(c[0][2*p],   aH[0], bh);
                mma_f16(c[0][2*p+1], aH[0], bh + 2);
                mma_f16(c[1][2*p],   aH[1], bh);
                mma_f16(c[1][2*p+1], aH[1], bh + 2);
                // pass A*Bl
                mma_f16(c[0][2*p],   aH[0], bl);
                mma_f16(c[0][2*p+1], aH[0], bl + 2);
                mma_f16(c[1][2*p],   aH[1], bl);
                mma_f16(c[1][2*p+1], aH[1], bl + 2);
            }
        }
    }

    // epilogue: bias + sigmoid -> g_F
    #pragma unroll
    for (int mt = 0; mt < 2; mt++) {
        #pragma unroll
        for (int nt = 0; nt < 8; nt++) {
            size_t m = r0 + mwarp * 32 + mt * 16 + g;
            int n = n0 + nwarp * 64 + nt * 8 + t4 * 2;
            float b0 = Vb[n], b1 = Vb[n + 1];
            float2 v0, v1;
            v0.x = sigmoidf_(c[mt][nt][0] + b0);
            v0.y = sigmoidf_(c[mt][nt][1] + b1);
            v1.x = sigmoidf_(c[mt][nt][2] + b0);
            v1.y = sigmoidf_(c[mt][nt][3] + b1);
            *reinterpret_cast<float2*>(g_F + m * DDIM + n) = v0;
            *reinterpret_cast<float2*>(g_F + (m + 8) * DDIM + n) = v1;
        }
    }
}

// ---------------- recurrence, segmented (affine composition) ----------------
__global__ __launch_bounds__(256) void recur_part_kernel()
{
    int gidx = blockIdx.x * blockDim.x + threadIdx.x;   // 0..262143
    int seg = gidx >> 15;
    int r   = gidx & 32767;
    int b = r >> 10;
    int d = r & 1023;
    const float* p = g_F + ((size_t)b * SEQ + seg * SEGLEN) * DDIM + d;
    float A = 1.0f, B = 0.0f;
    #pragma unroll 8
    for (int t = 0; t < SEGLEN; t++) {
        float f = p[(size_t)t * DDIM];
        A *= f;
        B = f * (B + 1.0f);
    }
    g_segA[gidx] = A;
    g_segB[gidx] = B;
}

__global__ __launch_bounds__(256) void recur_combine_kernel()
{
    int idx = blockIdx.x * blockDim.x + threadIdx.x;    // 0..32767
    float c = 0.0f;
    #pragma unroll
    for (int s = 0; s < RSEG; s++)
        c = g_segA[s * (BATCH * DDIM) + idx] * c + g_segB[s * (BATCH * DDIM) + idx];
    g_c[idx] = c;
}

// ---------------- o at last timestep + h ----------------
__global__ __launch_bounds__(256) void oh_kernel(
    const float* __restrict__ x,
    const float* __restrict__ Ww,
    const float* __restrict__ Vw,
    const float* __restrict__ Vb)
{
    int idx = blockIdx.x * blockDim.x + threadIdx.x;
    int b = idx >> 10;
    int d = idx & 1023;
    const float* xlast = x + ((size_t)b * SEQ + (SEQ - 1)) * INDIM;
    const float* xprev = xlast - INDIM;
    const float* wcol  = Ww + 2 * DDIM + d;
    const float* vcol  = Vw + 2 * DDIM + d;
    float acc = Vb[2 * DDIM + d];
    #pragma unroll 4
    for (int k = 0; k < INDIM; k++) {
        acc += xlast[k] * wcol[(size_t)k * (3 * DDIM)];
        acc += xprev[k] * vcol[(size_t)k * (3 * DDIM)];
    }
    g_h[idx] = g_c[idx] * sigmoidf_(acc);
}

// ---------------- MLP layers (M=32, N=2048) ----------------
__global__ __launch_bounds__(256) void mlp_kernel(
    const float* __restrict__ W,
    const float* __restrict__ bias,
    int KDIM, int layer)
{
    const float* Ain = (layer == 0) ? g_h  : g_q0;
    float*       out = (layer == 0) ? g_q0 : g_q1;

    __shared__ float As[32][33];
    __shared__ float Bs[32][33];

    int n0   = blockIdx.x * 32;
    int tid  = threadIdx.x;
    int tcol = tid & 31;
    int trow = tid >> 5;

    float acc[4] = {0.f, 0.f, 0.f, 0.f};

    for (int k0 = 0; k0 < KDIM; k0 += 32) {
        #pragma unroll
        for (int i = 0; i < 4; i++) {
            int lin = tid + i * 256;
            int m = lin >> 5, kk = lin & 31;
            As[m][kk] = Ain[(size_t)m * KDIM + k0 + kk];
            Bs[m][kk] = W[(size_t)(k0 + m) * MLPDIM + n0 + kk];
        }
        __syncthreads();
        #pragma unroll
        for (int kk = 0; kk < 32; kk++) {
            float bv = Bs[kk][tcol];
            #pragma unroll
            for (int i = 0; i < 4; i++)
                acc[i] += As[trow * 4 + i][kk] * bv;
        }
        __syncthreads();
    }
    #pragma unroll
    for (int i = 0; i < 4; i++) {
        float v = acc[i] + bias[n0 + tcol];
        out[(size_t)(trow * 4 + i) * MLPDIM + n0 + tcol] = fmaxf(v, 0.0f);
    }
}

// ---------------- head ----------------
__global__ __launch_bounds__(256) void head_kernel(
    const float* __restrict__ W2,
    const float* __restrict__ b2,
    float* __restrict__ out)
{
    int warp = (blockIdx.x * blockDim.x + threadIdx.x) >> 5;
    int lane = threadIdx.x & 31;
    if (warp >= BATCH * NCLS) return;
    int m = warp / NCLS;
    int n = warp % NCLS;
    const float* a = g_q1 + (size_t)m * MLPDIM;
    float s = 0.0f;
    for (int k = lane; k < MLPDIM; k += 32)
        s += a[k] * W2[(size_t)k * NCLS + n];
    #pragma unroll
    for (int off = 16; off; off >>= 1)
        s += __shfl_xor_sync(0xffffffffu, s, off);
    if (lane == 0) out[warp] = s + b2[n];
}

// ============================================================================
extern "C" void kernel_launch(void* const* d_in, const int* in_sizes, int n_in,
                              void* d_out, int out_size)
{
    const float* x   = (const float*)d_in[0];
    const float* Ww  = (const float*)d_in[1];
    const float* Vw  = (const float*)d_in[2];
    const float* Vb  = (const float*)d_in[3];
    const float* l0w = (const float*)d_in[4];
    const float* l0b = (const float*)d_in[5];
    const float* l1w = (const float*)d_in[6];
    const float* l1b = (const float*)d_in[7];
    const float* l2w = (const float*)d_in[8];
    const float* l2b = (const float*)d_in[9];
    float* out = (float*)d_out;

    cudaFuncSetAttribute(fgemm_mma_kernel,
                         cudaFuncAttributeMaxDynamicSharedMemorySize, SMEM_TOTAL);

    // 0. convert to fp16 scratch (A single, B hi/lo)
    convert_x_kernel<<<(BSROWS * 128) / 256, 256>>>(x);
    convert_w_kernel<<<dim3(KCAT / 32, DDIM / 32), 256>>>(Ww, Vw);

    // 1. f = sigmoid(x@Wf + xprev@Vf + b) via fp16 2-pass mma.sync
    fgemm_mma_kernel<<<dim3(DDIM / BN, BSROWS / BM), 256, SMEM_TOTAL>>>(Vb);

    // 2. recurrence -> c_last (segmented)
    recur_part_kernel<<<(RSEG * BATCH * DDIM) / 256, 256>>>();
    recur_combine_kernel<<<(BATCH * DDIM) / 256, 256>>>();

    // 3. o at last timestep, h = c * o
    oh_kernel<<<(BATCH * DDIM) / 256, 256>>>(x, Ww, Vw, Vb);

    // 4. MLP
    mlp_kernel<<<MLPDIM / 32, 256>>>(l0w, l0b, DDIM,   0);
    mlp_kernel<<<MLPDIM / 32, 256>>>(l1w, l1b, MLPDIM, 1);

    // 5. head
    head_kernel<<<(BATCH * NCLS * 32 + 255) / 256, 256>>>(l2w, l2b, out);
}

// round 14
// speedup vs baseline: 1.8840x; 1.4156x over previous
// R14: fgemm 2-pass -> 1-pass pure fp16 (A and B both single-rounded fp16).
// -50% MMA volume on the measured HMMA-pipe wall. Error budget: predicted
// ~1.5-2.5e-4 final (gate at 4e-4 -> revert). Rest unchanged from R13 PASS.
#include <cuda_runtime.h>
#include <cuda_fp16.h>
#include <cstdint>
#include <math.h>

// Problem constants
#define BATCH   32
#define SEQ     1024
#define INDIM   1024
#define DDIM    1024
#define MLPDIM  2048
#define NCLS    10
#define BSROWS  (BATCH * SEQ)     // 32768
#define KCAT    (2 * INDIM)       // 2048

// GEMM tiling
#define BM 128
#define BN 128
#define BK 32
#define NKCH (KCAT / BK)          // 64 k-chunks
#define XH   (INDIM / BK)         // 16 (chunks in first half)
#define ROWSTRIDE 40              // fp16 per smem row (32 data + 8 pad), 80 bytes
#define ARR_BYTES (128 * ROWSTRIDE * 2)      // 10240
#define STAGE_BYTES (2 * ARR_BYTES)          // 20480: A, B
#define SMEM_TOTAL (2 * STAGE_BYTES)         // 40960 -> 2 CTAs/SM (reg-bound)

// recurrence segmentation
#define RSEG 8
#define SEGLEN (SEQ / RSEG)       // 128

// ---------------- scratch (device globals) ----------------
__device__ __align__(16) __half g_ah[(size_t)BSROWS * INDIM];   // 64 MB (A fp16)
__device__ __align__(16) __half g_bh[(size_t)DDIM * KCAT];      // [n][k] B fp16

__device__ float g_F[(size_t)BSROWS * DDIM];   // f = sigmoid(f_pre)
__device__ float g_segA[RSEG * BATCH * DDIM];
__device__ float g_segB[RSEG * BATCH * DDIM];
__device__ float g_c[BATCH * DDIM];
__device__ float g_h[BATCH * DDIM];
__device__ float g_q0[BATCH * MLPDIM];
__device__ float g_q1[BATCH * MLPDIM];

__device__ __forceinline__ float sigmoidf_(float v) {
    return 1.0f / (1.0f + expf(-v));
}
__device__ __forceinline__ uint32_t smem_u32(const void* p) {
    uint32_t a;
    asm("{ .reg .u64 t; cvta.to.shared.u64 t, %1; cvt.u32.u64 %0, t; }" : "=r"(a) : "l"(p));
    return a;
}
__device__ __forceinline__ void cpasync16z(uint32_t dst, const void* gsrc, uint32_t srcbytes) {
    asm volatile("cp.async.cg.shared.global [%0], [%1], 16, %2;"
                 :: "r"(dst), "l"(__cvta_generic_to_global(gsrc)), "r"(srcbytes) : "memory");
}
__device__ __forceinline__ void cp_commit() {
    asm volatile("cp.async.commit_group;" ::: "memory");
}
template <int N>
__device__ __forceinline__ void cp_wait() {
    asm volatile("cp.async.wait_group %0;" :: "n"(N) : "memory");
}
__device__ __forceinline__ void ldsm_x4(uint32_t* r, uint32_t addr) {
    asm volatile("ldmatrix.sync.aligned.m8n8.x4.shared.b16 {%0,%1,%2,%3}, [%4];"
                 : "=r"(r[0]), "=r"(r[1]), "=r"(r[2]), "=r"(r[3]) : "r"(addr));
}
__device__ __forceinline__ void mma_f16(float* c, const uint32_t* a, const uint32_t* b) {
    asm volatile(
        "mma.sync.aligned.m16n8k16.row.col.f32.f16.f16.f32 "
        "{%0,%1,%2,%3}, {%4,%5,%6,%7}, {%8,%9}, {%0,%1,%2,%3};"
        : "+f"(c[0]), "+f"(c[1]), "+f"(c[2]), "+f"(c[3])
        : "r"(a[0]), "r"(a[1]), "r"(a[2]), "r"(a[3]), "r"(b[0]), "r"(b[1]));
}

// ---------------- convert x -> fp16 [r][0:1024] ----------------
__global__ __launch_bounds__(256) void convert_x_kernel(const float* __restrict__ x)
{
    size_t idx = (size_t)blockIdx.x * blockDim.x + threadIdx.x;  // BSROWS*128
    size_t r = idx >> 7;
    int j = (int)(idx & 127) * 8;

    const float4* src = reinterpret_cast<const float4*>(x + r * INDIM + j);
    float4 v0 = src[0], v1 = src[1];
    float vs[8] = {v0.x, v0.y, v0.z, v0.w, v1.x, v1.y, v1.z, v1.w};

    uint32_t hw[4];
    #pragma unroll
    for (int i = 0; i < 4; i++) {
        __half h0 = __float2half_rn(vs[2*i]);
        __half h1 = __float2half_rn(vs[2*i+1]);
        hw[i] = (uint32_t)__half_as_ushort(h0) | ((uint32_t)__half_as_ushort(h1) << 16);
    }
    reinterpret_cast<uint4*>(g_ah)[(r * INDIM + j) >> 3] = make_uint4(hw[0], hw[1], hw[2], hw[3]);
}

// ---------------- convert weights: Bcat^T [n][k] fp16 ----------------
__global__ __launch_bounds__(256) void convert_w_kernel(
    const float* __restrict__ Ww, const float* __restrict__ Vw)
{
    __shared__ float s[32][33];
    int kt = blockIdx.x;     // 0..63
    int nt = blockIdx.y;     // 0..31
    int k0 = kt * 32, n0 = nt * 32;
    int tid = threadIdx.x;

    const float* src = (k0 < INDIM) ? (Ww + (size_t)k0 * (3 * DDIM))
                                    : (Vw + (size_t)(k0 - INDIM) * (3 * DDIM));
    #pragma unroll
    for (int i = 0; i < 4; i++) {
        int lin = tid + i * 256;
        int kk = lin >> 5, nn = lin & 31;
        s[kk][nn] = src[(size_t)kk * (3 * DDIM) + n0 + nn];
    }
    __syncthreads();

    #pragma unroll
    for (int i = 0; i < 2; i++) {
        int lin = tid + i * 256;
        int nn = lin >> 4;
        int kp = lin & 15;
        float a = s[kp * 2][nn], b = s[kp * 2 + 1][nn];
        __half h0 = __float2half_rn(a);
        __half h1 = __float2half_rn(b);
        size_t off = ((size_t)(n0 + nn) * KCAT + k0 + kp * 2) >> 1;
        reinterpret_cast<uint32_t*>(g_bh)[off] =
            (uint32_t)__half_as_ushort(h0) | ((uint32_t)__half_as_ushort(h1) << 16);
    }
}

// ---------------- main GEMM: mma.sync fp16 single-pass ----------------
// grid (8 n, 256 m), 256 threads = 8 warps (4 m x 2 n), warp tile 32x64.
// 2 CTAs/SM; 2-stage pipe; one __syncthreads per k-chunk.
__global__ __launch_bounds__(256, 2) void fgemm_mma_kernel(const float* __restrict__ Vb)
{
    extern __shared__ __align__(16) char smem[];
    const uint32_t sbase = smem_u32(smem);
    const int tid = threadIdx.x;
    const int wid = tid >> 5, lane = tid & 31;
    const int mwarp = wid >> 1, nwarp = wid & 1;
    const int g = lane >> 2, t4 = lane & 3;

    const size_t r0 = (size_t)blockIdx.y * BM;
    const int n0 = blockIdx.x * BN;

    // ldmatrix per-lane byte offsets (80B row stride; conflict-free)
    const uint32_t a_off = (((lane >> 3) & 1) * 8 + (lane & 7)) * 80 + (lane >> 4) * 16;
    const uint32_t b_off = (((lane >> 4) & 1) * 8 + (lane & 7)) * 80 + ((lane >> 3) & 1) * 16;

    float c[2][8][4];
    #pragma unroll
    for (int mt = 0; mt < 2; mt++)
        #pragma unroll
        for (int nt = 0; nt < 8; nt++)
            #pragma unroll
            for (int i = 0; i < 4; i++) c[mt][nt][i] = 0.0f;

    // prefetch: 1024 16B chunks per stage (A, B), 256 threads -> 4 each
    auto prefetch = [&](int kc, int s) {
        const uint32_t st = sbase + (uint32_t)s * STAGE_BYTES;
        #pragma unroll
        for (int i = 0; i < 4; i++) {
            int cidx = tid + i * 256;
            if (cidx < 512) {
                // A: 128 rows x 4 chunks
                int row = cidx >> 2;
                int ch  = cidx & 3;
                uint32_t dst = st + row * 80 + ch * 16;
                const void* src;
                uint32_t sz = 16;
                if (kc < XH) {
                    src = g_ah + (r0 + row) * INDIM + kc * BK + ch * 8;
                } else {
                    bool z = (row == 0) && ((r0 & (SEQ - 1)) == 0);
                    src = z ? (const void*)g_ah
                            : (const void*)(g_ah + (r0 + row - 1) * INDIM + (kc - XH) * BK + ch * 8);
                    sz = z ? 0u : 16u;
                }
                cpasync16z(dst, src, sz);
            } else {
                // B: 128 rows x 4 chunks
                int cidx2 = cidx - 512;
                int row  = cidx2 >> 2;
                int ch   = cidx2 & 3;
                uint32_t dst = st + ARR_BYTES + row * 80 + ch * 16;
                cpasync16z(dst, g_bh + (size_t)(n0 + row) * KCAT + kc * BK + ch * 8, 16);
            }
        }
        cp_commit();
    };

    prefetch(0, 0);

    for (int kc = 0; kc < NKCH; kc++) {
        int s = kc & 1;
        cp_wait<0>();
        __syncthreads();
        // safe: stage (kc+1)&1 was last read at iteration kc-1; the barrier
        // above proves all warps have left it.
        if (kc + 1 < NKCH) prefetch(kc + 1, s ^ 1);

        const uint32_t sA = sbase + (uint32_t)s * STAGE_BYTES;
        const uint32_t sB = sA + ARR_BYTES;

        #pragma unroll
        for (int h = 0; h < 2; h++) {
            uint32_t aH[2][4];
            #pragma unroll
            for (int mt = 0; mt < 2; mt++) {
                uint32_t rb = (uint32_t)(mwarp * 32 + mt * 16) * 80 + h * 32;
                ldsm_x4(aH[mt], sA + rb + a_off);
            }
            #pragma unroll
            for (int p = 0; p < 4; p++) {
                uint32_t bh[4];
                uint32_t nb = (uint32_t)(nwarp * 64 + p * 16) * 80 + h * 32;
                ldsm_x4(bh, sB + nb + b_off);
                mma_f16(c[0][2*p],   aH[0], bh);
                mma_f16(c[0][2*p+1], aH[0], bh + 2);
                mma_f16(c[1][2*p],   aH[1], bh);
                mma_f16(c[1][2*p+1], aH[1], bh + 2);
            }
        }
    }

    // epilogue: bias + sigmoid -> g_F
    #pragma unroll
    for (int mt = 0; mt < 2; mt++) {
        #pragma unroll
        for (int nt = 0; nt < 8; nt++) {
            size_t m = r0 + mwarp * 32 + mt * 16 + g;
            int n = n0 + nwarp * 64 + nt * 8 + t4 * 2;
            float b0 = Vb[n], b1 = Vb[n + 1];
            float2 v0, v1;
            v0.x = sigmoidf_(c[mt][nt][0] + b0);
            v0.y = sigmoidf_(c[mt][nt][1] + b1);
            v1.x = sigmoidf_(c[mt][nt][2] + b0);
            v1.y = sigmoidf_(c[mt][nt][3] + b1);
            *reinterpret_cast<float2*>(g_F + m * DDIM + n) = v0;
            *reinterpret_cast<float2*>(g_F + (m + 8) * DDIM + n) = v1;
        }
    }
}

// ---------------- recurrence, segmented (affine composition) ----------------
__global__ __launch_bounds__(256) void recur_part_kernel()
{
    int gidx = blockIdx.x * blockDim.x + threadIdx.x;   // 0..262143
    int seg = gidx >> 15;
    int r   = gidx & 32767;
    int b = r >> 10;
    int d = r & 1023;
    const float* p = g_F + ((size_t)b * SEQ + seg * SEGLEN) * DDIM + d;
    float A = 1.0f, B = 0.0f;
    #pragma unroll 8
    for (int t = 0; t < SEGLEN; t++) {
        float f = p[(size_t)t * DDIM];
        A *= f;
        B = f * (B + 1.0f);
    }
    g_segA[gidx] = A;
    g_segB[gidx] = B;
}

__global__ __launch_bounds__(256) void recur_combine_kernel()
{
    int idx = blockIdx.x * blockDim.x + threadIdx.x;    // 0..32767
    float c = 0.0f;
    #pragma unroll
    for (int s = 0; s < RSEG; s++)
        c = g_segA[s * (BATCH * DDIM) + idx] * c + g_segB[s * (BATCH * DDIM) + idx];
    g_c[idx] = c;
}

// ---------------- o at last timestep + h ----------------
__global__ __launch_bounds__(256) void oh_kernel(
    const float* __restrict__ x,
    const float* __restrict__ Ww,
    const float* __restrict__ Vw,
    const float* __restrict__ Vb)
{
    int idx = blockIdx.x * blockDim.x + threadIdx.x;
    int b = idx >> 10;
    int d = idx & 1023;
    const float* xlast = x + ((size_t)b * SEQ + (SEQ - 1)) * INDIM;
    const float* xprev = xlast - INDIM;
    const float* wcol  = Ww + 2 * DDIM + d;
    const float* vcol  = Vw + 2 * DDIM + d;
    float acc = Vb[2 * DDIM + d];
    #pragma unroll 4
    for (int k = 0; k < INDIM; k++) {
        acc += xlast[k] * wcol[(size_t)k * (3 * DDIM)];
        acc += xprev[k] * vcol[(size_t)k * (3 * DDIM)];
    }
    g_h[idx] = g_c[idx] * sigmoidf_(acc);
}

// ---------------- MLP layers (M=32, N=2048) ----------------
__global__ __launch_bounds__(256) void mlp_kernel(
    const float* __restrict__ W,
    const float* __restrict__ bias,
    int KDIM, int layer)
{
    const float* Ain = (layer == 0) ? g_h  : g_q0;
    float*       out = (layer == 0) ? g_q0 : g_q1;

    __shared__ float As[32][33];
    __shared__ float Bs[32][33];

    int n0   = blockIdx.x * 32;
    int tid  = threadIdx.x;
    int tcol = tid & 31;
    int trow = tid >> 5;

    float acc[4] = {0.f, 0.f, 0.f, 0.f};

    for (int k0 = 0; k0 < KDIM; k0 += 32) {
        #pragma unroll
        for (int i = 0; i < 4; i++) {
            int lin = tid + i * 256;
            int m = lin >> 5, kk = lin & 31;
            As[m][kk] = Ain[(size_t)m * KDIM + k0 + kk];
            Bs[m][kk] = W[(size_t)(k0 + m) * MLPDIM + n0 + kk];
        }
        __syncthreads();
        #pragma unroll
        for (int kk = 0; kk < 32; kk++) {
            float bv = Bs[kk][tcol];
            #pragma unroll
            for (int i = 0; i < 4; i++)
                acc[i] += As[trow * 4 + i][kk] * bv;
        }
        __syncthreads();
    }
    #pragma unroll
    for (int i = 0; i < 4; i++) {
        float v = acc[i] + bias[n0 + tcol];
        out[(size_t)(trow * 4 + i) * MLPDIM + n0 + tcol] = fmaxf(v, 0.0f);
    }
}

// ---------------- head ----------------
__global__ __launch_bounds__(256) void head_kernel(
    const float* __restrict__ W2,
    const float* __restrict__ b2,
    float* __restrict__ out)
{
    int warp = (blockIdx.x * blockDim.x + threadIdx.x) >> 5;
    int lane = threadIdx.x & 31;
    if (warp >= BATCH * NCLS) return;
    int m = warp / NCLS;
    int n = warp % NCLS;
    const float* a = g_q1 + (size_t)m * MLPDIM;
    float s = 0.0f;
    for (int k = lane; k < MLPDIM; k += 32)
        s += a[k] * W2[(size_t)k * NCLS + n];
    #pragma unroll
    for (int off = 16; off; off >>= 1)
        s += __shfl_xor_sync(0xffffffffu, s, off);
    if (lane == 0) out[warp] = s + b2[n];
}

// ============================================================================
extern "C" void kernel_launch(void* const* d_in, const int* in_sizes, int n_in,
                              void* d_out, int out_size)
{
    const float* x   = (const float*)d_in[0];
    const float* Ww  = (const float*)d_in[1];
    const float* Vw  = (const float*)d_in[2];
    const float* Vb  = (const float*)d_in[3];
    const float* l0w = (const float*)d_in[4];
    const float* l0b = (const float*)d_in[5];
    const float* l1w = (const float*)d_in[6];
    const float* l1b = (const float*)d_in[7];
    const float* l2w = (const float*)d_in[8];
    const float* l2b = (const float*)d_in[9];
    float* out = (float*)d_out;

    cudaFuncSetAttribute(fgemm_mma_kernel,
                         cudaFuncAttributeMaxDynamicSharedMemorySize, SMEM_TOTAL);

    // 0. convert to fp16 scratch
    convert_x_kernel<<<(BSROWS * 128) / 256, 256>>>(x);
    convert_w_kernel<<<dim3(KCAT / 32, DDIM / 32), 256>>>(Ww, Vw);

    // 1. f = sigmoid(x@Wf + xprev@Vf + b) via fp16 mma.sync
    fgemm_mma_kernel<<<dim3(DDIM / BN, BSROWS / BM), 256, SMEM_TOTAL>>>(Vb);

    // 2. recurrence -> c_last (segmented)
    recur_part_kernel<<<(RSEG * BATCH * DDIM) / 256, 256>>>();
    recur_combine_kernel<<<(BATCH * DDIM) / 256, 256>>>();

    // 3. o at last timestep, h = c * o
    oh_kernel<<<(BATCH * DDIM) / 256, 256>>>(x, Ww, Vw, Vb);

    // 4. MLP
    mlp_kernel<<<MLPDIM / 32, 256>>>(l0w, l0b, DDIM,   0);
    mlp_kernel<<<MLPDIM / 32, 256>>>(l1w, l1b, MLPDIM, 1);

    // 5. head
    head_kernel<<<(BATCH * NCLS * 32 + 255) / 256, 256>>>(l2w, l2b, out);
}

// round 15
// speedup vs baseline: 2.1183x; 1.1244x over previous
// R15: (a) fgemm BK 32->64 (half the barriers/prefetch rounds); (b) fuse the
// segment recurrence scan into the fgemm epilogue via smem (kills the 256MB
// g_F round-trip and the recur_part kernel). 1-pass fp16 scheme from R14 PASS.
#include <cuda_runtime.h>
#include <cuda_fp16.h>
#include <cstdint>
#include <math.h>

// Problem constants
#define BATCH   32
#define SEQ     1024
#define INDIM   1024
#define DDIM    1024
#define MLPDIM  2048
#define NCLS    10
#define BSROWS  (BATCH * SEQ)     // 32768
#define KCAT    (2 * INDIM)       // 2048

// GEMM tiling
#define BM 128
#define BN 128
#define BK 64
#define NKCH (KCAT / BK)          // 32 k-chunks
#define XH   (INDIM / BK)         // 16 (chunks in first half)
#define RSTRIDE 144               // bytes per smem row (64 fp16 data + 8 pad)
#define ARR_BYTES (128 * RSTRIDE)            // 18432
#define STAGE_BYTES (2 * ARR_BYTES)          // 36864: A, B
#define SMEM_TOTAL (2 * STAGE_BYTES)         // 73728 -> 2 CTAs/SM
// epilogue reuse: sF[128][132] floats = 67584 B; sHA/sHB at 67584/68096

// recurrence segmentation
#define RSEG 8
#define SEGLEN (SEQ / RSEG)       // 128 == BM

// ---------------- scratch (device globals) ----------------
__device__ __align__(16) __half g_ah[(size_t)BSROWS * INDIM];   // 64 MB (A fp16)
__device__ __align__(16) __half g_bh[(size_t)DDIM * KCAT];      // [n][k] B fp16

__device__ float g_segA[RSEG * BATCH * DDIM];
__device__ float g_segB[RSEG * BATCH * DDIM];
__device__ float g_c[BATCH * DDIM];
__device__ float g_h[BATCH * DDIM];
__device__ float g_q0[BATCH * MLPDIM];
__device__ float g_q1[BATCH * MLPDIM];

__device__ __forceinline__ float sigmoidf_(float v) {
    return 1.0f / (1.0f + expf(-v));
}
__device__ __forceinline__ uint32_t smem_u32(const void* p) {
    uint32_t a;
    asm("{ .reg .u64 t; cvta.to.shared.u64 t, %1; cvt.u32.u64 %0, t; }" : "=r"(a) : "l"(p));
    return a;
}
__device__ __forceinline__ void cpasync16z(uint32_t dst, const void* gsrc, uint32_t srcbytes) {
    asm volatile("cp.async.cg.shared.global [%0], [%1], 16, %2;"
                 :: "r"(dst), "l"(__cvta_generic_to_global(gsrc)), "r"(srcbytes) : "memory");
}
__device__ __forceinline__ void cp_commit() {
    asm volatile("cp.async.commit_group;" ::: "memory");
}
template <int N>
__device__ __forceinline__ void cp_wait() {
    asm volatile("cp.async.wait_group %0;" :: "n"(N) : "memory");
}
__device__ __forceinline__ void ldsm_x4(uint32_t* r, uint32_t addr) {
    asm volatile("ldmatrix.sync.aligned.m8n8.x4.shared.b16 {%0,%1,%2,%3}, [%4];"
                 : "=r"(r[0]), "=r"(r[1]), "=r"(r[2]), "=r"(r[3]) : "r"(addr));
}
__device__ __forceinline__ void mma_f16(float* c, const uint32_t* a, const uint32_t* b) {
    asm volatile(
        "mma.sync.aligned.m16n8k16.row.col.f32.f16.f16.f32 "
        "{%0,%1,%2,%3}, {%4,%5,%6,%7}, {%8,%9}, {%0,%1,%2,%3};"
        : "+f"(c[0]), "+f"(c[1]), "+f"(c[2]), "+f"(c[3])
        : "r"(a[0]), "r"(a[1]), "r"(a[2]), "r"(a[3]), "r"(b[0]), "r"(b[1]));
}

// ---------------- convert x -> fp16 [r][0:1024] ----------------
__global__ __launch_bounds__(256) void convert_x_kernel(const float* __restrict__ x)
{
    size_t idx = (size_t)blockIdx.x * blockDim.x + threadIdx.x;  // BSROWS*128
    size_t r = idx >> 7;
    int j = (int)(idx & 127) * 8;

    const float4* src = reinterpret_cast<const float4*>(x + r * INDIM + j);
    float4 v0 = src[0], v1 = src[1];
    float vs[8] = {v0.x, v0.y, v0.z, v0.w, v1.x, v1.y, v1.z, v1.w};

    uint32_t hw[4];
    #pragma unroll
    for (int i = 0; i < 4; i++) {
        __half h0 = __float2half_rn(vs[2*i]);
        __half h1 = __float2half_rn(vs[2*i+1]);
        hw[i] = (uint32_t)__half_as_ushort(h0) | ((uint32_t)__half_as_ushort(h1) << 16);
    }
    reinterpret_cast<uint4*>(g_ah)[(r * INDIM + j) >> 3] = make_uint4(hw[0], hw[1], hw[2], hw[3]);
}

// ---------------- convert weights: Bcat^T [n][k] fp16 ----------------
__global__ __launch_bounds__(256) void convert_w_kernel(
    const float* __restrict__ Ww, const float* __restrict__ Vw)
{
    __shared__ float s[32][33];
    int kt = blockIdx.x;     // 0..63
    int nt = blockIdx.y;     // 0..31
    int k0 = kt * 32, n0 = nt * 32;
    int tid = threadIdx.x;

    const float* src = (k0 < INDIM) ? (Ww + (size_t)k0 * (3 * DDIM))
                                    : (Vw + (size_t)(k0 - INDIM) * (3 * DDIM));
    #pragma unroll
    for (int i = 0; i < 4; i++) {
        int lin = tid + i * 256;
        int kk = lin >> 5, nn = lin & 31;
        s[kk][nn] = src[(size_t)kk * (3 * DDIM) + n0 + nn];
    }
    __syncthreads();

    #pragma unroll
    for (int i = 0; i < 2; i++) {
        int lin = tid + i * 256;
        int nn = lin >> 4;
        int kp = lin & 15;
        float a = s[kp * 2][nn], b = s[kp * 2 + 1][nn];
        __half h0 = __float2half_rn(a);
        __half h1 = __float2half_rn(b);
        size_t off = ((size_t)(n0 + nn) * KCAT + k0 + kp * 2) >> 1;
        reinterpret_cast<uint32_t*>(g_bh)[off] =
            (uint32_t)__half_as_ushort(h0) | ((uint32_t)__half_as_ushort(h1) << 16);
    }
}

// ---------------- main GEMM + fused segment scan ----------------
// grid (8 n, 256 m), 256 threads = 8 warps (4 m x 2 n), warp tile 32x64.
// 2 CTAs/SM; 2-stage pipe; one __syncthreads per k-chunk; epilogue computes
// f = sigmoid(pre) into smem, then the per-(b,seg) affine scan -> g_segA/B.
__global__ __launch_bounds__(256, 2) void fgemm_mma_kernel(const float* __restrict__ Vb)
{
    extern __shared__ __align__(16) char smem[];
    const uint32_t sbase = smem_u32(smem);
    const int tid = threadIdx.x;
    const int wid = tid >> 5, lane = tid & 31;
    const int mwarp = wid >> 1, nwarp = wid & 1;
    const int g = lane >> 2, t4 = lane & 3;

    const size_t r0 = (size_t)blockIdx.y * BM;
    const int n0 = blockIdx.x * BN;

    // ldmatrix per-lane byte offsets (144B row stride; conflict-free)
    const uint32_t a_off = (((lane >> 3) & 1) * 8 + (lane & 7)) * RSTRIDE + (lane >> 4) * 16;
    const uint32_t b_off = (((lane >> 4) & 1) * 8 + (lane & 7)) * RSTRIDE + ((lane >> 3) & 1) * 16;

    float c[2][8][4];
    #pragma unroll
    for (int mt = 0; mt < 2; mt++)
        #pragma unroll
        for (int nt = 0; nt < 8; nt++)
            #pragma unroll
            for (int i = 0; i < 4; i++) c[mt][nt][i] = 0.0f;

    // prefetch: 2048 16B chunks per stage (A 128x8, B 128x8), 256 threads -> 8 each
    auto prefetch = [&](int kc, int s) {
        const uint32_t st = sbase + (uint32_t)s * STAGE_BYTES;
        #pragma unroll
        for (int i = 0; i < 8; i++) {
            int cidx = tid + i * 256;
            if (cidx < 1024) {
                // A: 128 rows x 8 chunks
                int row = cidx >> 3;
                int ch  = cidx & 7;
                uint32_t dst = st + row * RSTRIDE + ch * 16;
                const void* src;
                uint32_t sz = 16;
                if (kc < XH) {
                    src = g_ah + (r0 + row) * INDIM + kc * BK + ch * 8;
                } else {
                    bool z = (row == 0) && ((r0 & (SEQ - 1)) == 0);
                    src = z ? (const void*)g_ah
                            : (const void*)(g_ah + (r0 + row - 1) * INDIM + (kc - XH) * BK + ch * 8);
                    sz = z ? 0u : 16u;
                }
                cpasync16z(dst, src, sz);
            } else {
                // B: 128 rows x 8 chunks
                int cidx2 = cidx - 1024;
                int row  = cidx2 >> 3;
                int ch   = cidx2 & 7;
                uint32_t dst = st + ARR_BYTES + row * RSTRIDE + ch * 16;
                cpasync16z(dst, g_bh + (size_t)(n0 + row) * KCAT + kc * BK + ch * 8, 16);
            }
        }
        cp_commit();
    };

    prefetch(0, 0);

    for (int kc = 0; kc < NKCH; kc++) {
        int s = kc & 1;
        cp_wait<0>();
        __syncthreads();
        // safe: stage (kc+1)&1 was last read at iteration kc-1; the barrier
        // above proves all warps have left it.
        if (kc + 1 < NKCH) prefetch(kc + 1, s ^ 1);

        const uint32_t sA = sbase + (uint32_t)s * STAGE_BYTES;
        const uint32_t sB = sA + ARR_BYTES;

        #pragma unroll
        for (int h = 0; h < 4; h++) {          // four k16 steps (BK=64)
            uint32_t aH[2][4];
            #pragma unroll
            for (int mt = 0; mt < 2; mt++) {
                uint32_t rb = (uint32_t)(mwarp * 32 + mt * 16) * RSTRIDE + h * 32;
                ldsm_x4(aH[mt], sA + rb + a_off);
            }
            #pragma unroll
            for (int p = 0; p < 4; p++) {
                uint32_t bh[4];
                uint32_t nb = (uint32_t)(nwarp * 64 + p * 16) * RSTRIDE + h * 32;
                ldsm_x4(bh, sB + nb + b_off);
                mma_f16(c[0][2*p],   aH[0], bh);
                mma_f16(c[0][2*p+1], aH[0], bh + 2);
                mma_f16(c[1][2*p],   aH[1], bh);
                mma_f16(c[1][2*p+1], aH[1], bh + 2);
            }
        }
    }

    // ---- fused epilogue: f -> smem, segment affine scan -> g_segA/B ----
    __syncthreads();   // all warps done reading stages; smem is reusable

    float* sF = reinterpret_cast<float*>(smem);                    // [128][132]
    float* sHA = reinterpret_cast<float*>(smem + 67584);           // [128]
    float* sHB = reinterpret_cast<float*>(smem + 68096);           // [128]

    #pragma unroll
    for (int mt = 0; mt < 2; mt++) {
        #pragma unroll
        for (int nt = 0; nt < 8; nt++) {
            int m = mwarp * 32 + mt * 16 + g;       // 0..127 (t within segment)
            int col = nwarp * 64 + nt * 8 + t4 * 2; // 0..127
            float b0 = Vb[n0 + col], b1 = Vb[n0 + col + 1];
            sF[m * 132 + col]           = sigmoidf_(c[mt][nt][0] + b0);
            sF[m * 132 + col + 1]       = sigmoidf_(c[mt][nt][1] + b1);
            sF[(m + 8) * 132 + col]     = sigmoidf_(c[mt][nt][2] + b0);
            sF[(m + 8) * 132 + col + 1] = sigmoidf_(c[mt][nt][3] + b1);
        }
    }
    __syncthreads();

    // scan: c_t = f_t * (c_{t-1} + 1). Each column's 128-chain split in two
    // 64-halves (tid>>7 selects half), composed via smem.
    {
        int col = tid & 127;
        int half = tid >> 7;
        float A = 1.0f, B = 0.0f;
        const float* p = sF + (half * 64) * 132 + col;
        #pragma unroll 8
        for (int t = 0; t < 64; t++) {
            float f = p[t * 132];
            A *= f;
            B = f * (B + 1.0f);
        }
        if (half == 0) { sHA[col] = A; sHB[col] = B; }
        __syncthreads();
        if (half == 1) {
            float A0 = sHA[col], B0 = sHB[col];
            float Af = A0 * A;          // composite over 128 steps
            float Bf = A * B0 + B;
            int b   = (int)(r0 >> 10);          // batch
            int seg = (int)((r0 >> 7) & 7);     // segment within sequence
            size_t out = (size_t)seg * (BATCH * DDIM) + (size_t)b * DDIM + n0 + col;
            g_segA[out] = Af;
            g_segB[out] = Bf;
        }
    }
}

// ---------------- combine segments -> c_last ----------------
__global__ __launch_bounds__(256) void recur_combine_kernel()
{
    int idx = blockIdx.x * blockDim.x + threadIdx.x;    // 0..32767
    float c = 0.0f;
    #pragma unroll
    for (int s = 0; s < RSEG; s++)
        c = g_segA[s * (BATCH * DDIM) + idx] * c + g_segB[s * (BATCH * DDIM) + idx];
    g_c[idx] = c;
}

// ---------------- o at last timestep + h ----------------
__global__ __launch_bounds__(256) void oh_kernel(
    const float* __restrict__ x,
    const float* __restrict__ Ww,
    const float* __restrict__ Vw,
    const float* __restrict__ Vb)
{
    int idx = blockIdx.x * blockDim.x + threadIdx.x;
    int b = idx >> 10;
    int d = idx & 1023;
    const float* xlast = x + ((size_t)b * SEQ + (SEQ - 1)) * INDIM;
    const float* xprev = xlast - INDIM;
    const float* wcol  = Ww + 2 * DDIM + d;
    const float* vcol  = Vw + 2 * DDIM + d;
    float acc = Vb[2 * DDIM + d];
    #pragma unroll 4
    for (int k = 0; k < INDIM; k++) {
        acc += xlast[k] * wcol[(size_t)k * (3 * DDIM)];
        acc += xprev[k] * vcol[(size_t)k * (3 * DDIM)];
    }
    g_h[idx] = g_c[idx] * sigmoidf_(acc);
}

// ---------------- MLP layers (M=32, N=2048) ----------------
__global__ __launch_bounds__(256) void mlp_kernel(
    const float* __restrict__ W,
    const float* __restrict__ bias,
    int KDIM, int layer)
{
    const float* Ain = (layer == 0) ? g_h  : g_q0;
    float*       out = (layer == 0) ? g_q0 : g_q1;

    __shared__ float As[32][33];
    __shared__ float Bs[32][33];

    int n0   = blockIdx.x * 32;
    int tid  = threadIdx.x;
    int tcol = tid & 31;
    int trow = tid >> 5;

    float acc[4] = {0.f, 0.f, 0.f, 0.f};

    for (int k0 = 0; k0 < KDIM; k0 += 32) {
        #pragma unroll
        for (int i = 0; i < 4; i++) {
            int lin = tid + i * 256;
            int m = lin >> 5, kk = lin & 31;
            As[m][kk] = Ain[(size_t)m * KDIM + k0 + kk];
            Bs[m][kk] = W[(size_t)(k0 + m) * MLPDIM + n0 + kk];
        }
        __syncthreads();
        #pragma unroll
        for (int kk = 0; kk < 32; kk++) {
            float bv = Bs[kk][tcol];
            #pragma unroll
            for (int i = 0; i < 4; i++)
                acc[i] += As[trow * 4 + i][kk] * bv;
        }
        __syncthreads();
    }
    #pragma unroll
    for (int i = 0; i < 4; i++) {
        float v = acc[i] + bias[n0 + tcol];
        out[(size_t)(trow * 4 + i) * MLPDIM + n0 + tcol] = fmaxf(v, 0.0f);
    }
}

// ---------------- head ----------------
__global__ __launch_bounds__(256) void head_kernel(
    const float* __restrict__ W2,
    const float* __restrict__ b2,
    float* __restrict__ out)
{
    int warp = (blockIdx.x * blockDim.x + threadIdx.x) >> 5;
    int lane = threadIdx.x & 31;
    if (warp >= BATCH * NCLS) return;
    int m = warp / NCLS;
    int n = warp % NCLS;
    const float* a = g_q1 + (size_t)m * MLPDIM;
    float s = 0.0f;
    for (int k = lane; k < MLPDIM; k += 32)
        s += a[k] * W2[(size_t)k * NCLS + n];
    #pragma unroll
    for (int off = 16; off; off >>= 1)
        s += __shfl_xor_sync(0xffffffffu, s, off);
    if (lane == 0) out[warp] = s + b2[n];
}

// ============================================================================
extern "C" void kernel_launch(void* const* d_in, const int* in_sizes, int n_in,
                              void* d_out, int out_size)
{
    const float* x   = (const float*)d_in[0];
    const float* Ww  = (const float*)d_in[1];
    const float* Vw  = (const float*)d_in[2];
    const float* Vb  = (const float*)d_in[3];
    const float* l0w = (const float*)d_in[4];
    const float* l0b = (const float*)d_in[5];
    const float* l1w = (const float*)d_in[6];
    const float* l1b = (const float*)d_in[7];
    const float* l2w = (const float*)d_in[8];
    const float* l2b = (const float*)d_in[9];
    float* out = (float*)d_out;

    cudaFuncSetAttribute(fgemm_mma_kernel,
                         cudaFuncAttributeMaxDynamicSharedMemorySize, SMEM_TOTAL);

    // 0. convert to fp16 scratch
    convert_x_kernel<<<(BSROWS * 128) / 256, 256>>>(x);
    convert_w_kernel<<<dim3(KCAT / 32, DDIM / 32), 256>>>(Ww, Vw);

    // 1. f-gate GEMM + fused segment scan -> g_segA/g_segB
    fgemm_mma_kernel<<<dim3(DDIM / BN, BSROWS / BM), 256, SMEM_TOTAL>>>(Vb);

    // 2. combine segments -> c_last
    recur_combine_kernel<<<(BATCH * DDIM) / 256, 256>>>();

    // 3. o at last timestep, h = c * o
    oh_kernel<<<(BATCH * DDIM) / 256, 256>>>(x, Ww, Vw, Vb);

    // 4. MLP
    mlp_kernel<<<MLPDIM / 32, 256>>>(l0w, l0b, DDIM,   0);
    mlp_kernel<<<MLPDIM / 32, 256>>>(l1w, l1b, MLPDIM, 1);

    // 5. head
    head_kernel<<<(BATCH * NCLS * 32 + 255) / 256, 256>>>(l2w, l2b, out);
}